// round 2
// baseline (speedup 1.0000x reference)
#include <cuda_runtime.h>
#include <math.h>

#define TT 8192
#define IN_DIM 2048
#define OUT_DIM 2048
#define PROJ 512
#define NE 8
#define NSLOT (TT * 2)
#define PADROWS (NSLOT + NE * 128)   // 17408
#define MAXTILES (PADROWS / 128)     // 136

// ---------------- scratch (device globals; no allocations) ----------------
__device__ int   g_route_e[NSLOT];
__device__ float g_route_w[NSLOT];
__device__ int   g_bucket_slot[PADROWS];
__device__ int   g_pos[NSLOT];
__device__ int   g_tile_expert[MAXTILES];
__device__ int   g_tile_rowbase[MAXTILES];
__device__ float g_H[(size_t)PADROWS * PROJ];      // ~35.7 MB
__device__ float g_Y[(size_t)PADROWS * OUT_DIM];   // ~142.6 MB

__device__ __forceinline__ float gelu_f(float v) {
    const float c = 0.7978845608028654f;  // sqrt(2/pi)
    float inner = c * (v + 0.044715f * v * v * v);
    return 0.5f * v * (1.0f + tanhf(inner));
}

// ---------------- 1. gating: logits -> softmax -> top2 ----------------
__global__ __launch_bounds__(256) void gating_kernel(
    const float* __restrict__ x, const float* __restrict__ gw,
    const float* __restrict__ gb) {
    int warp = threadIdx.x >> 5, lane = threadIdx.x & 31;
    int t = blockIdx.x * 8 + warp;
    const float* xr = x + (size_t)t * IN_DIM;
    float acc[8] = {0.f, 0.f, 0.f, 0.f, 0.f, 0.f, 0.f, 0.f};
    for (int i = lane; i < IN_DIM; i += 32) {
        float xv = xr[i];
        const float4* g4 = (const float4*)(gw + (size_t)i * NE);
        float4 g0 = g4[0], g1 = g4[1];
        acc[0] += xv * g0.x; acc[1] += xv * g0.y;
        acc[2] += xv * g0.z; acc[3] += xv * g0.w;
        acc[4] += xv * g1.x; acc[5] += xv * g1.y;
        acc[6] += xv * g1.z; acc[7] += xv * g1.w;
    }
#pragma unroll
    for (int o = 16; o > 0; o >>= 1)
#pragma unroll
        for (int e = 0; e < 8; e++)
            acc[e] += __shfl_xor_sync(0xffffffffu, acc[e], o);
    if (lane == 0) {
        const float INV = 0.022097086912079608f;  // 1/sqrt(2048)
        float l[8], m = -1e30f;
#pragma unroll
        for (int e = 0; e < 8; e++) {
            l[e] = (acc[e] + gb[e]) * INV;
            m = fmaxf(m, l[e]);
        }
        float p[8], s = 0.f;
#pragma unroll
        for (int e = 0; e < 8; e++) { p[e] = expf(l[e] - m); s += p[e]; }
        int i1 = 0;
#pragma unroll
        for (int e = 1; e < 8; e++) if (l[e] > l[i1]) i1 = e;
        int i2 = (i1 == 0) ? 1 : 0;
#pragma unroll
        for (int e = 0; e < 8; e++) if (e != i1 && l[e] > l[i2]) i2 = e;
        float inv_s = 1.f / s;
        g_route_e[2 * t]     = i1; g_route_w[2 * t]     = p[i1] * inv_s;
        g_route_e[2 * t + 1] = i2; g_route_w[2 * t + 1] = p[i2] * inv_s;
    }
}

// ---------------- 2. deterministic bucketing (stable counting sort) ----------------
__global__ __launch_bounds__(256) void bucket_kernel() {
    __shared__ int hist[256][8];
    __shared__ int offs[256][8];
    __shared__ int tot[8];
    __shared__ int base[8];
    int tid = threadIdx.x;
    int cnt[8] = {0, 0, 0, 0, 0, 0, 0, 0};
    int s0 = tid * (NSLOT / 256);  // 64 slots per thread, contiguous (stable)
    for (int i = 0; i < NSLOT / 256; i++) cnt[g_route_e[s0 + i]]++;
#pragma unroll
    for (int e = 0; e < 8; e++) hist[tid][e] = cnt[e];
    for (int i = tid; i < MAXTILES; i += 256) g_tile_expert[i] = -1;
    for (int i = tid; i < PADROWS; i += 256) g_bucket_slot[i] = -1;
    __syncthreads();
    if (tid < 8) {
        int s = 0;
        for (int k = 0; k < 256; k++) s += hist[k][tid];
        tot[tid] = s;
    }
    __syncthreads();
    if (tid == 0) {
        int p = 0, tile = 0;
        for (int e = 0; e < 8; e++) {
            base[e] = p;
            int ntile = (tot[e] + 127) >> 7;
            for (int i = 0; i < ntile; i++) {
                g_tile_expert[tile] = e;
                g_tile_rowbase[tile] = p + i * 128;
                tile++;
            }
            p += ntile * 128;
        }
    }
    __syncthreads();
    if (tid < 8) {
        int r = base[tid];
        for (int k = 0; k < 256; k++) { offs[k][tid] = r; r += hist[k][tid]; }
    }
    __syncthreads();
    int o[8];
#pragma unroll
    for (int e = 0; e < 8; e++) o[e] = offs[tid][e];
    for (int i = 0; i < NSLOT / 256; i++) {
        int s = s0 + i;
        int e = g_route_e[s];
        int p = o[e]++;
        g_bucket_slot[p] = s;
        g_pos[s] = p;
    }
}

// =====================================================================
// 128x128x8 double-buffered SGEMM tile, 8x8 microtile (split 4+4)
// =====================================================================

// ---------------- 3. GEMM1: H = gelu(gather(x) @ w1[e] + b1[e]) ----------------
__global__ __launch_bounds__(256) void gemm1_kernel(
    const float* __restrict__ x, const float* __restrict__ w1,
    const float* __restrict__ b1) {
    int e = g_tile_expert[blockIdx.x];
    if (e < 0) return;
    int rowbase = g_tile_rowbase[blockIdx.x];
    int n0 = blockIdx.y * 128;
    __shared__ float As[2][8][132];
    __shared__ float Bs[2][8][128];
    __shared__ int s_tok[128];
    int tid = threadIdx.x;
    if (tid < 128) {
        int slot = g_bucket_slot[rowbase + tid];
        s_tok[tid] = (slot >= 0) ? (slot >> 1) : -1;
    }
    __syncthreads();

    const int a_m = tid >> 1;            // 0..127
    const int a_k = (tid & 1) << 2;      // 0 or 4
    const int b_k = tid >> 5;            // 0..7
    const int b_n = (tid & 31) << 2;     // 0..124
    const int tx = tid & 15;
    const int ty = tid >> 4;

    const int tok = s_tok[a_m];
    const float* aptr = x + (size_t)(tok < 0 ? 0 : tok) * IN_DIM + a_k;
    const float* bptr = w1 + (size_t)e * IN_DIM * PROJ + (size_t)b_k * PROJ + n0 + b_n;

    // first chunk
    float4 av = make_float4(0.f, 0.f, 0.f, 0.f);
    if (tok >= 0) av = *(const float4*)aptr;
    float4 bv = *(const float4*)bptr;
    As[0][a_k + 0][a_m] = av.x; As[0][a_k + 1][a_m] = av.y;
    As[0][a_k + 2][a_m] = av.z; As[0][a_k + 3][a_m] = av.w;
    *(float4*)&Bs[0][b_k][b_n] = bv;
    __syncthreads();

    float acc[8][8] = {};
    int buf = 0;
    for (int k0 = 8; k0 <= IN_DIM; k0 += 8) {
        float4 av2, bv2;
        const bool more = (k0 < IN_DIM);
        if (more) {
            av2 = make_float4(0.f, 0.f, 0.f, 0.f);
            if (tok >= 0) av2 = *(const float4*)(aptr + k0);
            bv2 = *(const float4*)(bptr + (size_t)k0 * PROJ);
        }
#pragma unroll
        for (int kk = 0; kk < 8; kk++) {
            float a[8], b[8];
            *(float4*)&a[0] = *(const float4*)&As[buf][kk][ty << 2];
            *(float4*)&a[4] = *(const float4*)&As[buf][kk][64 + (ty << 2)];
            *(float4*)&b[0] = *(const float4*)&Bs[buf][kk][tx << 2];
            *(float4*)&b[4] = *(const float4*)&Bs[buf][kk][64 + (tx << 2)];
#pragma unroll
            for (int i = 0; i < 8; i++)
#pragma unroll
                for (int j = 0; j < 8; j++) acc[i][j] += a[i] * b[j];
        }
        if (more) {
            int nb = buf ^ 1;
            As[nb][a_k + 0][a_m] = av2.x; As[nb][a_k + 1][a_m] = av2.y;
            As[nb][a_k + 2][a_m] = av2.z; As[nb][a_k + 3][a_m] = av2.w;
            *(float4*)&Bs[nb][b_k][b_n] = bv2;
            __syncthreads();
            buf = nb;
        }
    }

    // epilogue: bias + gelu -> g_H
    float bb[8];
    const float* b1e = b1 + (size_t)e * PROJ + n0;
    *(float4*)&bb[0] = *(const float4*)(b1e + (tx << 2));
    *(float4*)&bb[4] = *(const float4*)(b1e + 64 + (tx << 2));
#pragma unroll
    for (int ih = 0; ih < 2; ih++) {
#pragma unroll
        for (int i = 0; i < 4; i++) {
            int r = ih * 64 + (ty << 2) + i;
            float* hrow = g_H + (size_t)(rowbase + r) * PROJ + n0;
            float4 v0, v1;
            int ai = ih * 4 + i;
            v0.x = gelu_f(acc[ai][0] + bb[0]); v0.y = gelu_f(acc[ai][1] + bb[1]);
            v0.z = gelu_f(acc[ai][2] + bb[2]); v0.w = gelu_f(acc[ai][3] + bb[3]);
            v1.x = gelu_f(acc[ai][4] + bb[4]); v1.y = gelu_f(acc[ai][5] + bb[5]);
            v1.z = gelu_f(acc[ai][6] + bb[6]); v1.w = gelu_f(acc[ai][7] + bb[7]);
            *(float4*)(hrow + (tx << 2)) = v0;
            *(float4*)(hrow + 64 + (tx << 2)) = v1;
        }
    }
}

// ---------------- 4. GEMM2: Y = w * (H @ w2[e] + b2[e]) ----------------
__global__ __launch_bounds__(256) void gemm2_kernel(
    const float* __restrict__ w2, const float* __restrict__ b2) {
    int e = g_tile_expert[blockIdx.x];
    if (e < 0) return;
    int rowbase = g_tile_rowbase[blockIdx.x];
    int n0 = blockIdx.y * 128;
    __shared__ float As[2][8][132];
    __shared__ float Bs[2][8][128];
    __shared__ int s_slot[128];
    int tid = threadIdx.x;
    if (tid < 128) s_slot[tid] = g_bucket_slot[rowbase + tid];

    const int a_m = tid >> 1;
    const int a_k = (tid & 1) << 2;
    const int b_k = tid >> 5;
    const int b_n = (tid & 31) << 2;
    const int tx = tid & 15;
    const int ty = tid >> 4;

    const float* aptr = g_H + (size_t)(rowbase + a_m) * PROJ + a_k;
    const float* bptr = w2 + (size_t)e * PROJ * OUT_DIM + (size_t)b_k * OUT_DIM + n0 + b_n;

    float4 av = *(const float4*)aptr;
    float4 bv = *(const float4*)bptr;
    As[0][a_k + 0][a_m] = av.x; As[0][a_k + 1][a_m] = av.y;
    As[0][a_k + 2][a_m] = av.z; As[0][a_k + 3][a_m] = av.w;
    *(float4*)&Bs[0][b_k][b_n] = bv;
    __syncthreads();

    float acc[8][8] = {};
    int buf = 0;
    for (int k0 = 8; k0 <= PROJ; k0 += 8) {
        float4 av2, bv2;
        const bool more = (k0 < PROJ);
        if (more) {
            av2 = *(const float4*)(aptr + k0);
            bv2 = *(const float4*)(bptr + (size_t)k0 * OUT_DIM);
        }
#pragma unroll
        for (int kk = 0; kk < 8; kk++) {
            float a[8], b[8];
            *(float4*)&a[0] = *(const float4*)&As[buf][kk][ty << 2];
            *(float4*)&a[4] = *(const float4*)&As[buf][kk][64 + (ty << 2)];
            *(float4*)&b[0] = *(const float4*)&Bs[buf][kk][tx << 2];
            *(float4*)&b[4] = *(const float4*)&Bs[buf][kk][64 + (tx << 2)];
#pragma unroll
            for (int i = 0; i < 8; i++)
#pragma unroll
                for (int j = 0; j < 8; j++) acc[i][j] += a[i] * b[j];
        }
        if (more) {
            int nb = buf ^ 1;
            As[nb][a_k + 0][a_m] = av2.x; As[nb][a_k + 1][a_m] = av2.y;
            As[nb][a_k + 2][a_m] = av2.z; As[nb][a_k + 3][a_m] = av2.w;
            *(float4*)&Bs[nb][b_k][b_n] = bv2;
            __syncthreads();
            buf = nb;
        }
    }

    float bb[8];
    const float* b2e = b2 + (size_t)e * OUT_DIM + n0;
    *(float4*)&bb[0] = *(const float4*)(b2e + (tx << 2));
    *(float4*)&bb[4] = *(const float4*)(b2e + 64 + (tx << 2));
#pragma unroll
    for (int ih = 0; ih < 2; ih++) {
#pragma unroll
        for (int i = 0; i < 4; i++) {
            int r = ih * 64 + (ty << 2) + i;
            int slot = s_slot[r];
            if (slot < 0) continue;
            float w = g_route_w[slot];
            float* yrow = g_Y + (size_t)(rowbase + r) * OUT_DIM + n0;
            int ai = ih * 4 + i;
            float4 v0, v1;
            v0.x = w * (acc[ai][0] + bb[0]); v0.y = w * (acc[ai][1] + bb[1]);
            v0.z = w * (acc[ai][2] + bb[2]); v0.w = w * (acc[ai][3] + bb[3]);
            v1.x = w * (acc[ai][4] + bb[4]); v1.y = w * (acc[ai][5] + bb[5]);
            v1.z = w * (acc[ai][6] + bb[6]); v1.w = w * (acc[ai][7] + bb[7]);
            *(float4*)(yrow + (tx << 2)) = v0;
            *(float4*)(yrow + 64 + (tx << 2)) = v1;
        }
    }
}

// ---------------- 5. combine: out[t] = Y[pos(t,0)] + Y[pos(t,1)] ----------------
__global__ __launch_bounds__(256) void combine_kernel(float* __restrict__ out) {
    int idx = blockIdx.x * 256 + threadIdx.x;  // over TT * (OUT_DIM/4)
    int t = idx >> 9;                          // OUT_DIM/4 = 512 per token
    int c = idx & 511;
    int p0 = g_pos[2 * t], p1 = g_pos[2 * t + 1];
    float4 a = ((const float4*)(g_Y + (size_t)p0 * OUT_DIM))[c];
    float4 b = ((const float4*)(g_Y + (size_t)p1 * OUT_DIM))[c];
    ((float4*)out)[idx] = make_float4(a.x + b.x, a.y + b.y, a.z + b.z, a.w + b.w);
}

extern "C" void kernel_launch(void* const* d_in, const int* in_sizes, int n_in,
                              void* d_out, int out_size) {
    const float* x      = (const float*)d_in[0];
    const float* gate_w = (const float*)d_in[1];
    const float* gate_b = (const float*)d_in[2];
    const float* w1     = (const float*)d_in[3];
    const float* b1     = (const float*)d_in[4];
    const float* w2     = (const float*)d_in[5];
    const float* b2     = (const float*)d_in[6];
    float* out = (float*)d_out;

    gating_kernel<<<TT / 8, 256>>>(x, gate_w, gate_b);
    bucket_kernel<<<1, 256>>>();
    gemm1_kernel<<<dim3(MAXTILES, PROJ / 128), 256>>>(x, w1, b1);
    gemm2_kernel<<<dim3(MAXTILES, OUT_DIM / 128), 256>>>(w2, b2);
    combine_kernel<<<(TT * (OUT_DIM / 4)) / 256, 256>>>(out);
}

// round 6
// speedup vs baseline: 1.1346x; 1.1346x over previous
#include <cuda_runtime.h>
#include <cuda_bf16.h>
#include <mma.h>
#include <math.h>
#include <stdint.h>

using namespace nvcuda;

#define TT 8192
#define IN_DIM 2048
#define OUT_DIM 2048
#define PROJ 512
#define NE 8
#define NSLOT (TT * 2)
#define PADROWS (NSLOT + NE * 128)   // 17408
#define MAXTILES (PADROWS / 128)     // 136

// ---------------- device scratch ----------------
__device__ __align__(16) int   g_route_e[NSLOT];
__device__ __align__(16) float g_route_w[NSLOT];
__device__ __align__(16) int   g_bucket_slot[PADROWS];
__device__ __align__(16) int   g_pos[NSLOT];
__device__ __align__(16) int   g_tile_expert[MAXTILES];
__device__ __align__(16) int   g_tile_rowbase[MAXTILES];
__device__ __align__(16) float g_H[(size_t)PADROWS * PROJ];      // fp32 hidden
__device__ __align__(16) float g_Y[(size_t)PADROWS * OUT_DIM];

// ---------------- helpers ----------------
__device__ __forceinline__ void split2(float a, float b, uint32_t& h, uint32_t& l) {
    __nv_bfloat16 ah = __float2bfloat16(a), bh = __float2bfloat16(b);
    __nv_bfloat16 al = __float2bfloat16(a - __bfloat162float(ah));
    __nv_bfloat16 bl = __float2bfloat16(b - __bfloat162float(bh));
    h = (uint32_t)__bfloat16_as_ushort(ah) | ((uint32_t)__bfloat16_as_ushort(bh) << 16);
    l = (uint32_t)__bfloat16_as_ushort(al) | ((uint32_t)__bfloat16_as_ushort(bl) << 16);
}
__device__ __forceinline__ float gelu_f(float v) {
    const float c = 0.7978845608028654f;
    return 0.5f * v * (1.0f + tanhf(c * (v + 0.044715f * v * v * v)));
}

// ---------------- 1. gating (unchanged, validated R1) ----------------
__global__ __launch_bounds__(256) void gating_kernel(
    const float* __restrict__ x, const float* __restrict__ gw,
    const float* __restrict__ gb) {
    int warp = threadIdx.x >> 5, lane = threadIdx.x & 31;
    int t = blockIdx.x * 8 + warp;
    const float* xr = x + (size_t)t * IN_DIM;
    float acc[8] = {};
    for (int i = lane; i < IN_DIM; i += 32) {
        float xv = xr[i];
        const float4* g4 = (const float4*)(gw + (size_t)i * NE);
        float4 g0 = g4[0], g1 = g4[1];
        acc[0] += xv * g0.x; acc[1] += xv * g0.y; acc[2] += xv * g0.z; acc[3] += xv * g0.w;
        acc[4] += xv * g1.x; acc[5] += xv * g1.y; acc[6] += xv * g1.z; acc[7] += xv * g1.w;
    }
#pragma unroll
    for (int o = 16; o > 0; o >>= 1)
#pragma unroll
        for (int e = 0; e < 8; e++) acc[e] += __shfl_xor_sync(0xffffffffu, acc[e], o);
    if (lane == 0) {
        const float INV = 0.022097086912079608f;
        float l[8], m = -1e30f;
#pragma unroll
        for (int e = 0; e < 8; e++) { l[e] = (acc[e] + gb[e]) * INV; m = fmaxf(m, l[e]); }
        float p[8], s = 0.f;
#pragma unroll
        for (int e = 0; e < 8; e++) { p[e] = expf(l[e] - m); s += p[e]; }
        int i1 = 0;
#pragma unroll
        for (int e = 1; e < 8; e++) if (l[e] > l[i1]) i1 = e;
        int i2 = (i1 == 0) ? 1 : 0;
#pragma unroll
        for (int e = 0; e < 8; e++) if (e != i1 && l[e] > l[i2]) i2 = e;
        float inv_s = 1.f / s;
        g_route_e[2 * t] = i1;     g_route_w[2 * t] = p[i1] * inv_s;
        g_route_e[2 * t + 1] = i2; g_route_w[2 * t + 1] = p[i2] * inv_s;
    }
}

// ---------------- 2. bucketing (unchanged, validated) ----------------
__global__ __launch_bounds__(256) void bucket_kernel() {
    __shared__ int hist[256][8];
    __shared__ int offs[256][8];
    __shared__ int tot[8];
    __shared__ int base[8];
    int tid = threadIdx.x;
    int cnt[8] = {};
    int s0 = tid * (NSLOT / 256);
    for (int i = 0; i < NSLOT / 256; i++) cnt[g_route_e[s0 + i]]++;
#pragma unroll
    for (int e = 0; e < 8; e++) hist[tid][e] = cnt[e];
    for (int i = tid; i < MAXTILES; i += 256) g_tile_expert[i] = -1;
    for (int i = tid; i < PADROWS; i += 256) g_bucket_slot[i] = -1;
    __syncthreads();
    if (tid < 8) {
        int s = 0;
        for (int k = 0; k < 256; k++) s += hist[k][tid];
        tot[tid] = s;
    }
    __syncthreads();
    if (tid == 0) {
        int p = 0, tile = 0;
        for (int e = 0; e < 8; e++) {
            base[e] = p;
            int ntile = (tot[e] + 127) >> 7;
            for (int i = 0; i < ntile; i++) {
                g_tile_expert[tile] = e;
                g_tile_rowbase[tile] = p + i * 128;
                tile++;
            }
            p += ntile * 128;
        }
    }
    __syncthreads();
    if (tid < 8) {
        int r = base[tid];
        for (int k = 0; k < 256; k++) { offs[k][tid] = r; r += hist[k][tid]; }
    }
    __syncthreads();
    int o[8];
#pragma unroll
    for (int e = 0; e < 8; e++) o[e] = offs[tid][e];
    for (int i = 0; i < NSLOT / 256; i++) {
        int s = s0 + i;
        int e = g_route_e[s];
        int p = o[e]++;
        g_bucket_slot[p] = s;
        g_pos[s] = p;
    }
}

// ---------------- wmma GEMM: fp32 in, split bf16x3, fp32 out ----------------
// C(128x128) = A(128 x KTOT) @ W[e](KTOT x NDIM) slice, via wmma 16x16x16 bf16.
template <int KTOT, bool IS_G1>
__global__ __launch_bounds__(256, 2) void gemm_wmma_kernel(
    const float* __restrict__ A_src,   // x for G1 (gathered); unused for G2
    const float* __restrict__ W,       // w1 (E,IN,PROJ) or w2 (E,PROJ,OUT): [e][k][n]
    const float* __restrict__ bias) {
    constexpr int NC = KTOT / 16;
    constexpr int NDIM = IS_G1 ? PROJ : OUT_DIM;
    __shared__ __align__(16) __nv_bfloat16 sAh[2][128][16];
    __shared__ __align__(16) __nv_bfloat16 sAl[2][128][16];
    __shared__ __align__(16) __nv_bfloat16 sBh[2][16][128];
    __shared__ __align__(16) __nv_bfloat16 sBl[2][16][128];
    __shared__ __align__(16) float patch[8][256];
    __shared__ int tokS[128];
    __shared__ float biasS[128];

    const int e = g_tile_expert[blockIdx.x];
    if (e < 0) return;
    const int rowbase = g_tile_rowbase[blockIdx.x];
    const int n0 = blockIdx.y * 128;
    const int tid = threadIdx.x, lane = tid & 31, warp = tid >> 5;
    const int wm = warp >> 1, wn = warp & 1;   // warp tile: 32m x 64n

    if (tid < 128) {
        int slot = g_bucket_slot[rowbase + tid];
        tokS[tid] = IS_G1 ? (slot >= 0 ? (slot >> 1) : -1) : slot;
        biasS[tid] = bias[(size_t)e * NDIM + n0 + tid];
    }
    __syncthreads();

    // loader geometry: A = 128 rows x 16 k fp32; B = 16 k-rows x 128 n fp32
    const int lr = tid >> 1, lc8 = (tid & 1) * 8;
    const int bk = tid >> 4, bn8 = (tid & 15) * 8;
    const float* pA;
    bool avalid = true;
    if (IS_G1) {
        int tok = tokS[lr];
        if (tok < 0) { avalid = false; tok = 0; }
        pA = A_src + (size_t)tok * IN_DIM + lc8;
    } else {
        pA = g_H + (size_t)(rowbase + lr) * PROJ + lc8;
    }
    const float* pB = W + ((size_t)e * KTOT + bk) * NDIM + n0 + bn8;

    const float4 f4z = make_float4(0.f, 0.f, 0.f, 0.f);

#define LOADT(kidx)                                                            \
    do {                                                                       \
        const float* _pa = pA + (kidx) * 16;                                   \
        ra0 = avalid ? *(const float4*)(_pa) : f4z;                            \
        ra1 = avalid ? *(const float4*)(_pa + 4) : f4z;                        \
        const float* _pb = pB + (size_t)(kidx) * 16 * NDIM;                    \
        rb0 = *(const float4*)(_pb);                                           \
        rb1 = *(const float4*)(_pb + 4);                                       \
    } while (0)

#define STORET(bf)                                                             \
    do {                                                                       \
        uint32_t h0, l0, h1, l1, h2, l2, h3, l3;                               \
        split2(ra0.x, ra0.y, h0, l0); split2(ra0.z, ra0.w, h1, l1);            \
        split2(ra1.x, ra1.y, h2, l2); split2(ra1.z, ra1.w, h3, l3);            \
        *(uint4*)&sAh[bf][lr][lc8] = make_uint4(h0, h1, h2, h3);               \
        *(uint4*)&sAl[bf][lr][lc8] = make_uint4(l0, l1, l2, l3);               \
        split2(rb0.x, rb0.y, h0, l0); split2(rb0.z, rb0.w, h1, l1);            \
        split2(rb1.x, rb1.y, h2, l2); split2(rb1.z, rb1.w, h3, l3);            \
        *(uint4*)&sBh[bf][bk][bn8] = make_uint4(h0, h1, h2, h3);               \
        *(uint4*)&sBl[bf][bk][bn8] = make_uint4(l0, l1, l2, l3);               \
    } while (0)

    wmma::fragment<wmma::accumulator, 16, 16, 16, float> facc[2][4];
#pragma unroll
    for (int mi = 0; mi < 2; mi++)
#pragma unroll
        for (int ng = 0; ng < 4; ng++) wmma::fill_fragment(facc[mi][ng], 0.f);

    float4 ra0, ra1, rb0, rb1;
    LOADT(0);
    STORET(0);
    __syncthreads();

#pragma unroll 1
    for (int k = 0; k < NC; k++) {
        const int buf = k & 1;
        const bool more = (k + 1 < NC);
        if (more) LOADT(k + 1);

        wmma::fragment<wmma::matrix_a, 16, 16, 16, __nv_bfloat16, wmma::row_major> fah, fal;
        wmma::fragment<wmma::matrix_b, 16, 16, 16, __nv_bfloat16, wmma::row_major> fbh, fbl;
#pragma unroll
        for (int mi = 0; mi < 2; mi++) {
            wmma::load_matrix_sync(fah, &sAh[buf][wm * 32 + mi * 16][0], 16);
            wmma::load_matrix_sync(fal, &sAl[buf][wm * 32 + mi * 16][0], 16);
#pragma unroll
            for (int ng = 0; ng < 4; ng++) {
                wmma::load_matrix_sync(fbh, &sBh[buf][0][wn * 64 + ng * 16], 128);
                wmma::load_matrix_sync(fbl, &sBl[buf][0][wn * 64 + ng * 16], 128);
                wmma::mma_sync(facc[mi][ng], fah, fbh, facc[mi][ng]);
                wmma::mma_sync(facc[mi][ng], fal, fbh, facc[mi][ng]);
                wmma::mma_sync(facc[mi][ng], fah, fbl, facc[mi][ng]);
            }
        }
        if (more) {
            STORET(buf ^ 1);
            __syncthreads();
        }
    }

    // ---- epilogue via store_matrix_sync (API-owned layout) ----
    float* pw = patch[warp];
#pragma unroll
    for (int mi = 0; mi < 2; mi++)
#pragma unroll
        for (int ng = 0; ng < 4; ng++) {
            __syncwarp();
            wmma::store_matrix_sync(pw, facc[mi][ng], 16, wmma::mem_row_major);
            __syncwarp();
            const int r = lane >> 1;               // 0..15
            const int c0 = (lane & 1) * 8;         // 0 or 8
            const int mloc = wm * 32 + mi * 16 + r;
            const size_t grow = (size_t)rowbase + mloc;
            const int lcol = wn * 64 + ng * 16 + c0;
            if (IS_G1) {
                float* dst = g_H + grow * PROJ + n0 + lcol;
#pragma unroll
                for (int j = 0; j < 8; j++)
                    dst[j] = gelu_f(pw[r * 16 + c0 + j] + biasS[lcol + j]);
            } else {
                const int slot = tokS[mloc];
                if (slot >= 0) {
                    const float w = g_route_w[slot];
                    float* dst = g_Y + grow * OUT_DIM + n0 + lcol;
#pragma unroll
                    for (int j = 0; j < 8; j++)
                        dst[j] = w * (pw[r * 16 + c0 + j] + biasS[lcol + j]);
                }
            }
        }
#undef LOADT
#undef STORET
}

// ---------------- combine (unchanged, validated) ----------------
__global__ __launch_bounds__(256) void combine_kernel(float* __restrict__ out) {
    int idx = blockIdx.x * 256 + threadIdx.x;
    int t = idx >> 9;
    int c = idx & 511;
    int p0 = g_pos[2 * t], p1 = g_pos[2 * t + 1];
    float4 a = ((const float4*)(g_Y + (size_t)p0 * OUT_DIM))[c];
    float4 b = ((const float4*)(g_Y + (size_t)p1 * OUT_DIM))[c];
    ((float4*)out)[idx] = make_float4(a.x + b.x, a.y + b.y, a.z + b.z, a.w + b.w);
}

extern "C" void kernel_launch(void* const* d_in, const int* in_sizes, int n_in,
                              void* d_out, int out_size) {
    const float* x      = (const float*)d_in[0];
    const float* gate_w = (const float*)d_in[1];
    const float* gate_b = (const float*)d_in[2];
    const float* w1     = (const float*)d_in[3];
    const float* b1     = (const float*)d_in[4];
    const float* w2     = (const float*)d_in[5];
    const float* b2     = (const float*)d_in[6];
    float* out = (float*)d_out;

    gating_kernel<<<TT / 8, 256>>>(x, gate_w, gate_b);
    bucket_kernel<<<1, 256>>>();
    gemm_wmma_kernel<IN_DIM, true><<<dim3(MAXTILES, PROJ / 128), 256>>>(x, w1, b1);
    gemm_wmma_kernel<PROJ, false><<<dim3(MAXTILES, OUT_DIM / 128), 256>>>(x, w2, b2);
    combine_kernel<<<(TT * (OUT_DIM / 4)) / 256, 256>>>(out);
}

// round 7
// speedup vs baseline: 1.9694x; 1.7357x over previous
#include <cuda_runtime.h>
#include <cuda_bf16.h>
#include <mma.h>
#include <math.h>
#include <stdint.h>

using namespace nvcuda;

#define TT 8192
#define IN_DIM 2048
#define OUT_DIM 2048
#define PROJ 512
#define NE 8
#define NSLOT (TT * 2)
#define PADROWS (NSLOT + NE * 128)   // 17408
#define MAXTILES (PADROWS / 128)     // 136

#define APAD 24     // sA row stride (elements): conflict-free ldmatrix
#define BPAD 136    // sB row stride (elements): conflict-free ldmatrix

// ---------------- device scratch ----------------
__device__ __align__(16) int   g_route_e[NSLOT];
__device__ __align__(16) float g_route_w[NSLOT];
__device__ __align__(16) int   g_bucket_slot[PADROWS];
__device__ __align__(16) int   g_pos[NSLOT];
__device__ __align__(16) int   g_tile_expert[MAXTILES];
__device__ __align__(16) int   g_tile_rowbase[MAXTILES];
__device__ __align__(16) float g_H[(size_t)PADROWS * PROJ];      // fp32 hidden
__device__ __align__(16) float g_Y[(size_t)PADROWS * OUT_DIM];

// ---------------- helpers ----------------
__device__ __forceinline__ void split2(float a, float b, uint32_t& h, uint32_t& l) {
    __nv_bfloat16 ah = __float2bfloat16(a), bh = __float2bfloat16(b);
    __nv_bfloat16 al = __float2bfloat16(a - __bfloat162float(ah));
    __nv_bfloat16 bl = __float2bfloat16(b - __bfloat162float(bh));
    h = (uint32_t)__bfloat16_as_ushort(ah) | ((uint32_t)__bfloat16_as_ushort(bh) << 16);
    l = (uint32_t)__bfloat16_as_ushort(al) | ((uint32_t)__bfloat16_as_ushort(bl) << 16);
}
__device__ __forceinline__ float gelu_f(float v) {
    const float c = 0.7978845608028654f;
    return 0.5f * v * (1.0f + tanhf(c * (v + 0.044715f * v * v * v)));
}

// ---------------- 1. gating (validated) ----------------
__global__ __launch_bounds__(256) void gating_kernel(
    const float* __restrict__ x, const float* __restrict__ gw,
    const float* __restrict__ gb) {
    int warp = threadIdx.x >> 5, lane = threadIdx.x & 31;
    int t = blockIdx.x * 8 + warp;
    const float* xr = x + (size_t)t * IN_DIM;
    float acc[8] = {};
    for (int i = lane; i < IN_DIM; i += 32) {
        float xv = xr[i];
        const float4* g4 = (const float4*)(gw + (size_t)i * NE);
        float4 g0 = g4[0], g1 = g4[1];
        acc[0] += xv * g0.x; acc[1] += xv * g0.y; acc[2] += xv * g0.z; acc[3] += xv * g0.w;
        acc[4] += xv * g1.x; acc[5] += xv * g1.y; acc[6] += xv * g1.z; acc[7] += xv * g1.w;
    }
#pragma unroll
    for (int o = 16; o > 0; o >>= 1)
#pragma unroll
        for (int e = 0; e < 8; e++) acc[e] += __shfl_xor_sync(0xffffffffu, acc[e], o);
    if (lane == 0) {
        const float INV = 0.022097086912079608f;
        float l[8], m = -1e30f;
#pragma unroll
        for (int e = 0; e < 8; e++) { l[e] = (acc[e] + gb[e]) * INV; m = fmaxf(m, l[e]); }
        float p[8], s = 0.f;
#pragma unroll
        for (int e = 0; e < 8; e++) { p[e] = expf(l[e] - m); s += p[e]; }
        int i1 = 0;
#pragma unroll
        for (int e = 1; e < 8; e++) if (l[e] > l[i1]) i1 = e;
        int i2 = (i1 == 0) ? 1 : 0;
#pragma unroll
        for (int e = 0; e < 8; e++) if (e != i1 && l[e] > l[i2]) i2 = e;
        float inv_s = 1.f / s;
        g_route_e[2 * t] = i1;     g_route_w[2 * t] = p[i1] * inv_s;
        g_route_e[2 * t + 1] = i2; g_route_w[2 * t + 1] = p[i2] * inv_s;
    }
}

// ---------------- 2. bucketing (validated) ----------------
__global__ __launch_bounds__(256) void bucket_kernel() {
    __shared__ int hist[256][8];
    __shared__ int offs[256][8];
    __shared__ int tot[8];
    __shared__ int base[8];
    int tid = threadIdx.x;
    int cnt[8] = {};
    int s0 = tid * (NSLOT / 256);
    for (int i = 0; i < NSLOT / 256; i++) cnt[g_route_e[s0 + i]]++;
#pragma unroll
    for (int e = 0; e < 8; e++) hist[tid][e] = cnt[e];
    for (int i = tid; i < MAXTILES; i += 256) g_tile_expert[i] = -1;
    for (int i = tid; i < PADROWS; i += 256) g_bucket_slot[i] = -1;
    __syncthreads();
    if (tid < 8) {
        int s = 0;
        for (int k = 0; k < 256; k++) s += hist[k][tid];
        tot[tid] = s;
    }
    __syncthreads();
    if (tid == 0) {
        int p = 0, tile = 0;
        for (int e = 0; e < 8; e++) {
            base[e] = p;
            int ntile = (tot[e] + 127) >> 7;
            for (int i = 0; i < ntile; i++) {
                g_tile_expert[tile] = e;
                g_tile_rowbase[tile] = p + i * 128;
                tile++;
            }
            p += ntile * 128;
        }
    }
    __syncthreads();
    if (tid < 8) {
        int r = base[tid];
        for (int k = 0; k < 256; k++) { offs[k][tid] = r; r += hist[k][tid]; }
    }
    __syncthreads();
    int o[8];
#pragma unroll
    for (int e = 0; e < 8; e++) o[e] = offs[tid][e];
    for (int i = 0; i < NSLOT / 256; i++) {
        int s = s0 + i;
        int e = g_route_e[s];
        int p = o[e]++;
        g_bucket_slot[p] = s;
        g_pos[s] = p;
    }
}

// ---------------- wmma GEMM: padded smem, hoisted fragments ----------------
template <int KTOT, bool IS_G1>
__global__ __launch_bounds__(256, 2) void gemm_wmma_kernel(
    const float* __restrict__ A_src,
    const float* __restrict__ W,       // [e][k][n]
    const float* __restrict__ bias) {
    constexpr int NC = KTOT / 16;
    constexpr int NDIM = IS_G1 ? PROJ : OUT_DIM;
    __shared__ __align__(16) __nv_bfloat16 sAh[2][128][APAD];
    __shared__ __align__(16) __nv_bfloat16 sAl[2][128][APAD];
    __shared__ __align__(16) __nv_bfloat16 sBh[2][16][BPAD];
    __shared__ __align__(16) __nv_bfloat16 sBl[2][16][BPAD];
    __shared__ int tokS[128];
    __shared__ float biasS[128];

    const int e = g_tile_expert[blockIdx.x];
    if (e < 0) return;
    const int rowbase = g_tile_rowbase[blockIdx.x];
    const int n0 = blockIdx.y * 128;
    const int tid = threadIdx.x, lane = tid & 31, warp = tid >> 5;
    const int wm = warp >> 1, wn = warp & 1;   // warp tile: 32m x 64n

    if (tid < 128) {
        int slot = g_bucket_slot[rowbase + tid];
        tokS[tid] = IS_G1 ? (slot >= 0 ? (slot >> 1) : -1) : slot;
        biasS[tid] = bias[(size_t)e * NDIM + n0 + tid];
    }
    __syncthreads();

    // loader geometry
    const int lr = tid >> 1, lc8 = (tid & 1) * 8;
    const int bk = tid >> 4, bn8 = (tid & 15) * 8;
    const float* pA;
    bool avalid = true;
    if (IS_G1) {
        int tok = tokS[lr];
        if (tok < 0) { avalid = false; tok = 0; }
        pA = A_src + (size_t)tok * IN_DIM + lc8;
    } else {
        pA = g_H + (size_t)(rowbase + lr) * PROJ + lc8;
    }
    const float* pB = W + ((size_t)e * KTOT + bk) * NDIM + n0 + bn8;

    const float4 f4z = make_float4(0.f, 0.f, 0.f, 0.f);

#define LOADT(kidx)                                                            \
    do {                                                                       \
        const float* _pa = pA + (kidx) * 16;                                   \
        ra0 = avalid ? *(const float4*)(_pa) : f4z;                            \
        ra1 = avalid ? *(const float4*)(_pa + 4) : f4z;                        \
        const float* _pb = pB + (size_t)(kidx) * 16 * NDIM;                    \
        rb0 = *(const float4*)(_pb);                                           \
        rb1 = *(const float4*)(_pb + 4);                                       \
    } while (0)

#define STORET(bf)                                                             \
    do {                                                                       \
        uint32_t h0, l0, h1, l1, h2, l2, h3, l3;                               \
        split2(ra0.x, ra0.y, h0, l0); split2(ra0.z, ra0.w, h1, l1);            \
        split2(ra1.x, ra1.y, h2, l2); split2(ra1.z, ra1.w, h3, l3);            \
        *(uint4*)&sAh[bf][lr][lc8] = make_uint4(h0, h1, h2, h3);               \
        *(uint4*)&sAl[bf][lr][lc8] = make_uint4(l0, l1, l2, l3);               \
        split2(rb0.x, rb0.y, h0, l0); split2(rb0.z, rb0.w, h1, l1);            \
        split2(rb1.x, rb1.y, h2, l2); split2(rb1.z, rb1.w, h3, l3);            \
        *(uint4*)&sBh[bf][bk][bn8] = make_uint4(h0, h1, h2, h3);               \
        *(uint4*)&sBl[bf][bk][bn8] = make_uint4(l0, l1, l2, l3);               \
    } while (0)

    wmma::fragment<wmma::accumulator, 16, 16, 16, float> facc[2][4];
#pragma unroll
    for (int mi = 0; mi < 2; mi++)
#pragma unroll
        for (int ng = 0; ng < 4; ng++) wmma::fill_fragment(facc[mi][ng], 0.f);

    float4 ra0, ra1, rb0, rb1;
    LOADT(0);
    STORET(0);
    __syncthreads();

#pragma unroll 1
    for (int k = 0; k < NC; k++) {
        const int buf = k & 1;
        const bool more = (k + 1 < NC);
        if (more) LOADT(k + 1);

        // preload A fragments once (4 loads), B loaded once per ng (8 loads)
        wmma::fragment<wmma::matrix_a, 16, 16, 16, __nv_bfloat16, wmma::row_major> fah[2], fal[2];
#pragma unroll
        for (int mi = 0; mi < 2; mi++) {
            wmma::load_matrix_sync(fah[mi], &sAh[buf][wm * 32 + mi * 16][0], APAD);
            wmma::load_matrix_sync(fal[mi], &sAl[buf][wm * 32 + mi * 16][0], APAD);
        }
#pragma unroll
        for (int ng = 0; ng < 4; ng++) {
            wmma::fragment<wmma::matrix_b, 16, 16, 16, __nv_bfloat16, wmma::row_major> fbh, fbl;
            wmma::load_matrix_sync(fbh, &sBh[buf][0][wn * 64 + ng * 16], BPAD);
            wmma::load_matrix_sync(fbl, &sBl[buf][0][wn * 64 + ng * 16], BPAD);
#pragma unroll
            for (int mi = 0; mi < 2; mi++) {
                wmma::mma_sync(facc[mi][ng], fah[mi], fbh, facc[mi][ng]);
                wmma::mma_sync(facc[mi][ng], fal[mi], fbh, facc[mi][ng]);
                wmma::mma_sync(facc[mi][ng], fah[mi], fbl, facc[mi][ng]);
            }
        }
        if (more) {
            STORET(buf ^ 1);
            __syncthreads();
        }
    }

    // ---- epilogue: reuse sAh as per-warp patch buffer ----
    __syncthreads();   // all warps done reading tiles before overwrite
    float* pw = (float*)sAh + warp * 256;
#pragma unroll
    for (int mi = 0; mi < 2; mi++)
#pragma unroll
        for (int ng = 0; ng < 4; ng++) {
            __syncwarp();
            wmma::store_matrix_sync(pw, facc[mi][ng], 16, wmma::mem_row_major);
            __syncwarp();
            const int r = lane >> 1;               // 0..15
            const int c0 = (lane & 1) * 8;         // 0 or 8
            const int mloc = wm * 32 + mi * 16 + r;
            const size_t grow = (size_t)rowbase + mloc;
            const int lcol = wn * 64 + ng * 16 + c0;
            if (IS_G1) {
                float* dst = g_H + grow * PROJ + n0 + lcol;
#pragma unroll
                for (int j = 0; j < 8; j++)
                    dst[j] = gelu_f(pw[r * 16 + c0 + j] + biasS[lcol + j]);
            } else {
                const int slot = tokS[mloc];
                if (slot >= 0) {
                    const float w = g_route_w[slot];
                    float* dst = g_Y + grow * OUT_DIM + n0 + lcol;
#pragma unroll
                    for (int j = 0; j < 8; j++)
                        dst[j] = w * (pw[r * 16 + c0 + j] + biasS[lcol + j]);
                }
            }
        }
#undef LOADT
#undef STORET
}

// ---------------- combine (validated) ----------------
__global__ __launch_bounds__(256) void combine_kernel(float* __restrict__ out) {
    int idx = blockIdx.x * 256 + threadIdx.x;
    int t = idx >> 9;
    int c = idx & 511;
    int p0 = g_pos[2 * t], p1 = g_pos[2 * t + 1];
    float4 a = ((const float4*)(g_Y + (size_t)p0 * OUT_DIM))[c];
    float4 b = ((const float4*)(g_Y + (size_t)p1 * OUT_DIM))[c];
    ((float4*)out)[idx] = make_float4(a.x + b.x, a.y + b.y, a.z + b.z, a.w + b.w);
}

extern "C" void kernel_launch(void* const* d_in, const int* in_sizes, int n_in,
                              void* d_out, int out_size) {
    const float* x      = (const float*)d_in[0];
    const float* gate_w = (const float*)d_in[1];
    const float* gate_b = (const float*)d_in[2];
    const float* w1     = (const float*)d_in[3];
    const float* b1     = (const float*)d_in[4];
    const float* w2     = (const float*)d_in[5];
    const float* b2     = (const float*)d_in[6];
    float* out = (float*)d_out;

    gating_kernel<<<TT / 8, 256>>>(x, gate_w, gate_b);
    bucket_kernel<<<1, 256>>>();
    gemm_wmma_kernel<IN_DIM, true><<<dim3(MAXTILES, PROJ / 128), 256>>>(x, w1, b1);
    gemm_wmma_kernel<PROJ, false><<<dim3(MAXTILES, OUT_DIM / 128), 256>>>(x, w2, b2);
    combine_kernel<<<(TT * (OUT_DIM / 4)) / 256, 256>>>(out);
}

// round 9
// speedup vs baseline: 2.0709x; 1.0515x over previous
#include <cuda_runtime.h>
#include <cuda_bf16.h>
#include <mma.h>
#include <math.h>
#include <stdint.h>

using namespace nvcuda;

#define TT 8192
#define IN_DIM 2048
#define OUT_DIM 2048
#define PROJ 512
#define NE 8
#define NSLOT (TT * 2)
#define PADROWS (NSLOT + NE * 128)   // 17408
#define MAXTILES (PADROWS / 128)     // 136

#define APAD 24     // sA row stride (elements): conflict-free ldmatrix, 16B-aligned rows
#define BPAD 136    // sB row stride (elements): conflict-free ldmatrix, 16B-aligned rows

// ---------------- device scratch ----------------
__device__ __align__(16) int   g_route_e[NSLOT];
__device__ __align__(16) float g_route_w[NSLOT];
__device__ __align__(16) int   g_bucket_slot[PADROWS];
__device__ __align__(16) int   g_pos[NSLOT];
__device__ __align__(16) int   g_tile_expert[MAXTILES];
__device__ __align__(16) int   g_tile_rowbase[MAXTILES];
__device__ __align__(16) __nv_bfloat16 g_x_h[(size_t)TT * IN_DIM];
__device__ __align__(16) __nv_bfloat16 g_x_l[(size_t)TT * IN_DIM];
__device__ __align__(16) __nv_bfloat16 g_w1_h[(size_t)NE * IN_DIM * PROJ];
__device__ __align__(16) __nv_bfloat16 g_w1_l[(size_t)NE * IN_DIM * PROJ];
__device__ __align__(16) __nv_bfloat16 g_w2_h[(size_t)NE * PROJ * OUT_DIM];
__device__ __align__(16) __nv_bfloat16 g_w2_l[(size_t)NE * PROJ * OUT_DIM];
__device__ __align__(16) __nv_bfloat16 g_Hh[(size_t)PADROWS * PROJ];
__device__ __align__(16) __nv_bfloat16 g_Hl[(size_t)PADROWS * PROJ];
__device__ __align__(16) float g_Y[(size_t)PADROWS * OUT_DIM];

// ---------------- helpers ----------------
__device__ __forceinline__ void split2(float a, float b, uint32_t& h, uint32_t& l) {
    __nv_bfloat16 ah = __float2bfloat16(a), bh = __float2bfloat16(b);
    __nv_bfloat16 al = __float2bfloat16(a - __bfloat162float(ah));
    __nv_bfloat16 bl = __float2bfloat16(b - __bfloat162float(bh));
    h = (uint32_t)__bfloat16_as_ushort(ah) | ((uint32_t)__bfloat16_as_ushort(bh) << 16);
    l = (uint32_t)__bfloat16_as_ushort(al) | ((uint32_t)__bfloat16_as_ushort(bl) << 16);
}
__device__ __forceinline__ float gelu_f(float v) {
    const float c = 0.7978845608028654f;
    return 0.5f * v * (1.0f + tanhf(c * (v + 0.044715f * v * v * v)));
}
__device__ __forceinline__ uint32_t smem_u32(const void* p) {
    uint32_t a;
    asm("{ .reg .u64 t; cvta.to.shared.u64 t, %1; cvt.u32.u64 %0, t; }" : "=r"(a) : "l"(p));
    return a;
}
#define CP_ASYNC(dst, src, sz) \
    asm volatile("cp.async.cg.shared.global [%0], [%1], 16, %2;" \
                 :: "r"(dst), "l"(src), "r"(sz) : "memory")
#define CP_COMMIT() asm volatile("cp.async.commit_group;" ::: "memory")
#define CP_WAIT0() asm volatile("cp.async.wait_group 0;" ::: "memory")

// ---------------- 1. gating (validated) ----------------
__global__ __launch_bounds__(256) void gating_kernel(
    const float* __restrict__ x, const float* __restrict__ gw,
    const float* __restrict__ gb) {
    int warp = threadIdx.x >> 5, lane = threadIdx.x & 31;
    int t = blockIdx.x * 8 + warp;
    const float* xr = x + (size_t)t * IN_DIM;
    float acc[8] = {};
    for (int i = lane; i < IN_DIM; i += 32) {
        float xv = xr[i];
        const float4* g4 = (const float4*)(gw + (size_t)i * NE);
        float4 g0 = g4[0], g1 = g4[1];
        acc[0] += xv * g0.x; acc[1] += xv * g0.y; acc[2] += xv * g0.z; acc[3] += xv * g0.w;
        acc[4] += xv * g1.x; acc[5] += xv * g1.y; acc[6] += xv * g1.z; acc[7] += xv * g1.w;
    }
#pragma unroll
    for (int o = 16; o > 0; o >>= 1)
#pragma unroll
        for (int e = 0; e < 8; e++) acc[e] += __shfl_xor_sync(0xffffffffu, acc[e], o);
    if (lane == 0) {
        const float INV = 0.022097086912079608f;
        float l[8], m = -1e30f;
#pragma unroll
        for (int e = 0; e < 8; e++) { l[e] = (acc[e] + gb[e]) * INV; m = fmaxf(m, l[e]); }
        float p[8], s = 0.f;
#pragma unroll
        for (int e = 0; e < 8; e++) { p[e] = expf(l[e] - m); s += p[e]; }
        int i1 = 0;
#pragma unroll
        for (int e = 1; e < 8; e++) if (l[e] > l[i1]) i1 = e;
        int i2 = (i1 == 0) ? 1 : 0;
#pragma unroll
        for (int e = 0; e < 8; e++) if (e != i1 && l[e] > l[i2]) i2 = e;
        float inv_s = 1.f / s;
        g_route_e[2 * t] = i1;     g_route_w[2 * t] = p[i1] * inv_s;
        g_route_e[2 * t + 1] = i2; g_route_w[2 * t + 1] = p[i2] * inv_s;
    }
}

// ---------------- 2. bucketing (validated) ----------------
__global__ __launch_bounds__(256) void bucket_kernel() {
    __shared__ int hist[256][8];
    __shared__ int offs[256][8];
    __shared__ int tot[8];
    __shared__ int base[8];
    int tid = threadIdx.x;
    int cnt[8] = {};
    int s0 = tid * (NSLOT / 256);
    for (int i = 0; i < NSLOT / 256; i++) cnt[g_route_e[s0 + i]]++;
#pragma unroll
    for (int e = 0; e < 8; e++) hist[tid][e] = cnt[e];
    for (int i = tid; i < MAXTILES; i += 256) g_tile_expert[i] = -1;
    for (int i = tid; i < PADROWS; i += 256) g_bucket_slot[i] = -1;
    __syncthreads();
    if (tid < 8) {
        int s = 0;
        for (int k = 0; k < 256; k++) s += hist[k][tid];
        tot[tid] = s;
    }
    __syncthreads();
    if (tid == 0) {
        int p = 0, tile = 0;
        for (int e = 0; e < 8; e++) {
            base[e] = p;
            int ntile = (tot[e] + 127) >> 7;
            for (int i = 0; i < ntile; i++) {
                g_tile_expert[tile] = e;
                g_tile_rowbase[tile] = p + i * 128;
                tile++;
            }
            p += ntile * 128;
        }
    }
    __syncthreads();
    if (tid < 8) {
        int r = base[tid];
        for (int k = 0; k < 256; k++) { offs[k][tid] = r; r += hist[k][tid]; }
    }
    __syncthreads();
    int o[8];
#pragma unroll
    for (int e = 0; e < 8; e++) o[e] = offs[tid][e];
    for (int i = 0; i < NSLOT / 256; i++) {
        int s = s0 + i;
        int e = g_route_e[s];
        int p = o[e]++;
        g_bucket_slot[p] = s;
        g_pos[s] = p;
    }
}

// ---------------- fp32 -> bf16 hi/lo split; destinations resolved IN DEVICE CODE ----------------
__global__ __launch_bounds__(256) void fsplit_kernel(const float* __restrict__ src, int which) {
    __nv_bfloat16 *dh, *dl;
    if (which == 0)      { dh = g_x_h;  dl = g_x_l;  }
    else if (which == 1) { dh = g_w1_h; dl = g_w1_l; }
    else                 { dh = g_w2_h; dl = g_w2_l; }
    size_t i = (size_t)blockIdx.x * 256 + threadIdx.x;   // per 4 floats
    float4 v = ((const float4*)src)[i];
    uint32_t h0, l0, h1, l1;
    split2(v.x, v.y, h0, l0);
    split2(v.z, v.w, h1, l1);
    ((uint2*)dh)[i] = make_uint2(h0, h1);
    ((uint2*)dl)[i] = make_uint2(l0, l1);
}

// ---------------- wmma GEMM: pre-split bf16 operands, cp.async 2-stage ----------------
template <int KTOT, bool IS_G1>
__global__ __launch_bounds__(256, 2) void gemm_wmma_kernel(const float* __restrict__ bias) {
    constexpr int NC = KTOT / 16;
    constexpr int NDIM = IS_G1 ? PROJ : OUT_DIM;
    __shared__ __align__(16) __nv_bfloat16 sAh[2][128][APAD];
    __shared__ __align__(16) __nv_bfloat16 sAl[2][128][APAD];
    __shared__ __align__(16) __nv_bfloat16 sBh[2][16][BPAD];
    __shared__ __align__(16) __nv_bfloat16 sBl[2][16][BPAD];
    __shared__ int tokS[128];
    __shared__ float biasS[128];

    const int e = g_tile_expert[blockIdx.x];
    if (e < 0) return;
    const int rowbase = g_tile_rowbase[blockIdx.x];
    const int n0 = blockIdx.y * 128;
    const int tid = threadIdx.x, lane = tid & 31, warp = tid >> 5;
    const int wm = warp >> 1, wn = warp & 1;   // warp tile: 32m x 64n

    if (tid < 128) {
        int slot = g_bucket_slot[rowbase + tid];
        tokS[tid] = IS_G1 ? (slot >= 0 ? (slot >> 1) : -1) : slot;
        biasS[tid] = bias[(size_t)e * NDIM + n0 + tid];
    }
    __syncthreads();

    // loader geometry: A row = tid>>1 (16B chunk tid&1); B krow = tid>>4, nchunk = (tid&15)*8
    const int lr = tid >> 1, lc8 = (tid & 1) * 8;
    const int bk = tid >> 4, bn8 = (tid & 15) * 8;
    const __nv_bfloat16 *pAh, *pAl;
    uint32_t valA = 16;
    if (IS_G1) {
        int tok = tokS[lr];
        if (tok < 0) { valA = 0; tok = 0; }
        pAh = g_x_h + (size_t)tok * IN_DIM + lc8;
        pAl = g_x_l + (size_t)tok * IN_DIM + lc8;
    } else {
        pAh = g_Hh + (size_t)(rowbase + lr) * PROJ + lc8;
        pAl = g_Hl + (size_t)(rowbase + lr) * PROJ + lc8;
    }
    const __nv_bfloat16* Wh = IS_G1 ? g_w1_h : g_w2_h;
    const __nv_bfloat16* Wl = IS_G1 ? g_w1_l : g_w2_l;
    const __nv_bfloat16* pBh = Wh + ((size_t)e * KTOT + bk) * NDIM + n0 + bn8;
    const __nv_bfloat16* pBl = Wl + ((size_t)e * KTOT + bk) * NDIM + n0 + bn8;

    const uint32_t dAh = smem_u32(&sAh[0][lr][lc8]);
    const uint32_t dAl = smem_u32(&sAl[0][lr][lc8]);
    const uint32_t dBh = smem_u32(&sBh[0][bk][bn8]);
    const uint32_t dBl = smem_u32(&sBl[0][bk][bn8]);
    constexpr uint32_t stA = 128 * APAD * 2;   // bytes per A stage
    constexpr uint32_t stB = 16 * BPAD * 2;    // bytes per B stage

#define ISSUE(kidx)                                                         \
    do {                                                                    \
        const uint32_t _b = (uint32_t)((kidx) & 1);                         \
        const size_t _ka = (size_t)(kidx) * 16;                             \
        CP_ASYNC(dAh + _b * stA, pAh + _ka, valA);                          \
        CP_ASYNC(dAl + _b * stA, pAl + _ka, valA);                          \
        CP_ASYNC(dBh + _b * stB, pBh + _ka * NDIM, 16);                     \
        CP_ASYNC(dBl + _b * stB, pBl + _ka * NDIM, 16);                     \
        CP_COMMIT();                                                        \
    } while (0)

    wmma::fragment<wmma::accumulator, 16, 16, 16, float> facc[2][4];
#pragma unroll
    for (int mi = 0; mi < 2; mi++)
#pragma unroll
        for (int ng = 0; ng < 4; ng++) wmma::fill_fragment(facc[mi][ng], 0.f);

    ISSUE(0);

#pragma unroll 1
    for (int k = 0; k < NC; k++) {
        const int buf = k & 1;
        CP_WAIT0();
        __syncthreads();          // stage k visible to all; readers of k-1 done
        if (k + 1 < NC) ISSUE(k + 1);

        wmma::fragment<wmma::matrix_a, 16, 16, 16, __nv_bfloat16, wmma::row_major> fah[2], fal[2];
#pragma unroll
        for (int mi = 0; mi < 2; mi++) {
            wmma::load_matrix_sync(fah[mi], &sAh[buf][wm * 32 + mi * 16][0], APAD);
            wmma::load_matrix_sync(fal[mi], &sAl[buf][wm * 32 + mi * 16][0], APAD);
        }
#pragma unroll
        for (int ng = 0; ng < 4; ng++) {
            wmma::fragment<wmma::matrix_b, 16, 16, 16, __nv_bfloat16, wmma::row_major> fbh, fbl;
            wmma::load_matrix_sync(fbh, &sBh[buf][0][wn * 64 + ng * 16], BPAD);
            wmma::load_matrix_sync(fbl, &sBl[buf][0][wn * 64 + ng * 16], BPAD);
#pragma unroll
            for (int mi = 0; mi < 2; mi++) {
                wmma::mma_sync(facc[mi][ng], fah[mi], fbh, facc[mi][ng]);
                wmma::mma_sync(facc[mi][ng], fal[mi], fbh, facc[mi][ng]);
                wmma::mma_sync(facc[mi][ng], fah[mi], fbl, facc[mi][ng]);
            }
        }
        __syncthreads();          // all readers done before next overwrite
    }

    // ---- epilogue: reuse sAh as per-warp patch buffer ----
    float* pw = (float*)sAh + warp * 256;
#pragma unroll
    for (int mi = 0; mi < 2; mi++)
#pragma unroll
        for (int ng = 0; ng < 4; ng++) {
            __syncwarp();
            wmma::store_matrix_sync(pw, facc[mi][ng], 16, wmma::mem_row_major);
            __syncwarp();
            const int r = lane >> 1;               // 0..15
            const int c0 = (lane & 1) * 8;         // 0 or 8
            const int mloc = wm * 32 + mi * 16 + r;
            const size_t grow = (size_t)rowbase + mloc;
            const int lcol = wn * 64 + ng * 16 + c0;
            if (IS_G1) {
                float v[8];
#pragma unroll
                for (int j = 0; j < 8; j++)
                    v[j] = gelu_f(pw[r * 16 + c0 + j] + biasS[lcol + j]);
                uint32_t h[4], l[4];
#pragma unroll
                for (int q = 0; q < 4; q++) split2(v[2 * q], v[2 * q + 1], h[q], l[q]);
                *(uint4*)(g_Hh + grow * PROJ + n0 + lcol) = make_uint4(h[0], h[1], h[2], h[3]);
                *(uint4*)(g_Hl + grow * PROJ + n0 + lcol) = make_uint4(l[0], l[1], l[2], l[3]);
            } else {
                const int slot = tokS[mloc];
                if (slot >= 0) {
                    const float w = g_route_w[slot];
                    float* dst = g_Y + grow * OUT_DIM + n0 + lcol;
#pragma unroll
                    for (int j = 0; j < 8; j++)
                        dst[j] = w * (pw[r * 16 + c0 + j] + biasS[lcol + j]);
                }
            }
        }
#undef ISSUE
}

// ---------------- combine (validated) ----------------
__global__ __launch_bounds__(256) void combine_kernel(float* __restrict__ out) {
    int idx = blockIdx.x * 256 + threadIdx.x;
    int t = idx >> 9;
    int c = idx & 511;
    int p0 = g_pos[2 * t], p1 = g_pos[2 * t + 1];
    float4 a = ((const float4*)(g_Y + (size_t)p0 * OUT_DIM))[c];
    float4 b = ((const float4*)(g_Y + (size_t)p1 * OUT_DIM))[c];
    ((float4*)out)[idx] = make_float4(a.x + b.x, a.y + b.y, a.z + b.z, a.w + b.w);
}

extern "C" void kernel_launch(void* const* d_in, const int* in_sizes, int n_in,
                              void* d_out, int out_size) {
    const float* x      = (const float*)d_in[0];
    const float* gate_w = (const float*)d_in[1];
    const float* gate_b = (const float*)d_in[2];
    const float* w1     = (const float*)d_in[3];
    const float* b1     = (const float*)d_in[4];
    const float* w2     = (const float*)d_in[5];
    const float* b2     = (const float*)d_in[6];
    float* out = (float*)d_out;

    fsplit_kernel<<<(TT * IN_DIM / 4) / 256, 256>>>(x, 0);
    fsplit_kernel<<<((size_t)NE * IN_DIM * PROJ / 4) / 256, 256>>>(w1, 1);
    fsplit_kernel<<<((size_t)NE * PROJ * OUT_DIM / 4) / 256, 256>>>(w2, 2);
    gating_kernel<<<TT / 8, 256>>>(x, gate_w, gate_b);
    bucket_kernel<<<1, 256>>>();
    gemm_wmma_kernel<IN_DIM, true><<<dim3(MAXTILES, PROJ / 128), 256>>>(b1);
    gemm_wmma_kernel<PROJ, false><<<dim3(MAXTILES, OUT_DIM / 128), 256>>>(b2);
    combine_kernel<<<(TT * (OUT_DIM / 4)) / 256, 256>>>(out);
}

// round 10
// speedup vs baseline: 2.1103x; 1.0190x over previous
#include <cuda_runtime.h>
#include <cuda_bf16.h>
#include <mma.h>
#include <math.h>
#include <stdint.h>

using namespace nvcuda;

#define TT 8192
#define IN_DIM 2048
#define OUT_DIM 2048
#define PROJ 512
#define NE 8
#define NSLOT (TT * 2)
#define PADROWS (NSLOT + NE * 128)   // 17408
#define MAXTILES (PADROWS / 128)     // 136

#define APAD 24     // sA row stride (elements)
#define BPAD 136    // sB row stride (elements)
// dynamic smem stage layout (bytes)
#define OFF_AL 6144
#define OFF_BH 12288
#define OFF_BL 16640
#define STG 20992
#define NSTAGE 3
#define SOFF_TOK (NSTAGE * STG)          // 62976
#define SOFF_BIAS (SOFF_TOK + 512)
#define SMEM_DYN (SOFF_BIAS + 512)       // 64000

// ---------------- device scratch ----------------
__device__ __align__(16) int   g_route_e[NSLOT];
__device__ __align__(16) float g_route_w[NSLOT];
__device__ __align__(16) int   g_bucket_slot[PADROWS];
__device__ __align__(16) int   g_pos[NSLOT];
__device__ __align__(16) int   g_tile_expert[MAXTILES];
__device__ __align__(16) int   g_tile_rowbase[MAXTILES];
__device__ __align__(16) __nv_bfloat16 g_x_h[(size_t)TT * IN_DIM];
__device__ __align__(16) __nv_bfloat16 g_x_l[(size_t)TT * IN_DIM];
__device__ __align__(16) __nv_bfloat16 g_w1_h[(size_t)NE * IN_DIM * PROJ];
__device__ __align__(16) __nv_bfloat16 g_w1_l[(size_t)NE * IN_DIM * PROJ];
__device__ __align__(16) __nv_bfloat16 g_w2_h[(size_t)NE * PROJ * OUT_DIM];
__device__ __align__(16) __nv_bfloat16 g_w2_l[(size_t)NE * PROJ * OUT_DIM];
__device__ __align__(16) __nv_bfloat16 g_Hh[(size_t)PADROWS * PROJ];
__device__ __align__(16) __nv_bfloat16 g_Hl[(size_t)PADROWS * PROJ];
__device__ __align__(16) float g_Y[(size_t)PADROWS * OUT_DIM];

// ---------------- helpers ----------------
__device__ __forceinline__ void split2(float a, float b, uint32_t& h, uint32_t& l) {
    __nv_bfloat16 ah = __float2bfloat16(a), bh = __float2bfloat16(b);
    __nv_bfloat16 al = __float2bfloat16(a - __bfloat162float(ah));
    __nv_bfloat16 bl = __float2bfloat16(b - __bfloat162float(bh));
    h = (uint32_t)__bfloat16_as_ushort(ah) | ((uint32_t)__bfloat16_as_ushort(bh) << 16);
    l = (uint32_t)__bfloat16_as_ushort(al) | ((uint32_t)__bfloat16_as_ushort(bl) << 16);
}
__device__ __forceinline__ float gelu_f(float v) {
    const float c = 0.7978845608028654f;
    return 0.5f * v * (1.0f + tanhf(c * (v + 0.044715f * v * v * v)));
}
__device__ __forceinline__ uint32_t smem_u32(const void* p) {
    uint32_t a;
    asm("{ .reg .u64 t; cvta.to.shared.u64 t, %1; cvt.u32.u64 %0, t; }" : "=r"(a) : "l"(p));
    return a;
}
#define CP_ASYNC(dst, src, sz) \
    asm volatile("cp.async.cg.shared.global [%0], [%1], 16, %2;" \
                 :: "r"(dst), "l"(src), "r"(sz) : "memory")
#define CP_COMMIT() asm volatile("cp.async.commit_group;" ::: "memory")
#define CP_WAIT1() asm volatile("cp.async.wait_group 1;" ::: "memory")

// ---------------- 1. gating + x hi/lo split (fused) ----------------
__global__ __launch_bounds__(256) void gating_kernel(
    const float* __restrict__ x, const float* __restrict__ gw,
    const float* __restrict__ gb) {
    int warp = threadIdx.x >> 5, lane = threadIdx.x & 31;
    int t = blockIdx.x * 8 + warp;
    const float* xr = x + (size_t)t * IN_DIM;
    __nv_bfloat16* xh = g_x_h + (size_t)t * IN_DIM;
    __nv_bfloat16* xl = g_x_l + (size_t)t * IN_DIM;
    float acc[8] = {};
    for (int i = lane; i < IN_DIM; i += 32) {
        float xv = xr[i];
        __nv_bfloat16 hh = __float2bfloat16(xv);
        xh[i] = hh;
        xl[i] = __float2bfloat16(xv - __bfloat162float(hh));
        const float4* g4 = (const float4*)(gw + (size_t)i * NE);
        float4 g0 = g4[0], g1 = g4[1];
        acc[0] += xv * g0.x; acc[1] += xv * g0.y; acc[2] += xv * g0.z; acc[3] += xv * g0.w;
        acc[4] += xv * g1.x; acc[5] += xv * g1.y; acc[6] += xv * g1.z; acc[7] += xv * g1.w;
    }
#pragma unroll
    for (int o = 16; o > 0; o >>= 1)
#pragma unroll
        for (int e = 0; e < 8; e++) acc[e] += __shfl_xor_sync(0xffffffffu, acc[e], o);
    if (lane == 0) {
        const float INV = 0.022097086912079608f;
        float l[8], m = -1e30f;
#pragma unroll
        for (int e = 0; e < 8; e++) { l[e] = (acc[e] + gb[e]) * INV; m = fmaxf(m, l[e]); }
        float p[8], s = 0.f;
#pragma unroll
        for (int e = 0; e < 8; e++) { p[e] = expf(l[e] - m); s += p[e]; }
        int i1 = 0;
#pragma unroll
        for (int e = 1; e < 8; e++) if (l[e] > l[i1]) i1 = e;
        int i2 = (i1 == 0) ? 1 : 0;
#pragma unroll
        for (int e = 0; e < 8; e++) if (e != i1 && l[e] > l[i2]) i2 = e;
        float inv_s = 1.f / s;
        g_route_e[2 * t] = i1;     g_route_w[2 * t] = p[i1] * inv_s;
        g_route_e[2 * t + 1] = i2; g_route_w[2 * t + 1] = p[i2] * inv_s;
    }
}

// ---------------- 2. bucketing (validated) ----------------
__global__ __launch_bounds__(256) void bucket_kernel() {
    __shared__ int hist[256][8];
    __shared__ int offs[256][8];
    __shared__ int tot[8];
    __shared__ int base[8];
    int tid = threadIdx.x;
    int cnt[8] = {};
    int s0 = tid * (NSLOT / 256);
    for (int i = 0; i < NSLOT / 256; i++) cnt[g_route_e[s0 + i]]++;
#pragma unroll
    for (int e = 0; e < 8; e++) hist[tid][e] = cnt[e];
    for (int i = tid; i < MAXTILES; i += 256) g_tile_expert[i] = -1;
    for (int i = tid; i < PADROWS; i += 256) g_bucket_slot[i] = -1;
    __syncthreads();
    if (tid < 8) {
        int s = 0;
        for (int k = 0; k < 256; k++) s += hist[k][tid];
        tot[tid] = s;
    }
    __syncthreads();
    if (tid == 0) {
        int p = 0, tile = 0;
        for (int e = 0; e < 8; e++) {
            base[e] = p;
            int ntile = (tot[e] + 127) >> 7;
            for (int i = 0; i < ntile; i++) {
                g_tile_expert[tile] = e;
                g_tile_rowbase[tile] = p + i * 128;
                tile++;
            }
            p += ntile * 128;
        }
    }
    __syncthreads();
    if (tid < 8) {
        int r = base[tid];
        for (int k = 0; k < 256; k++) { offs[k][tid] = r; r += hist[k][tid]; }
    }
    __syncthreads();
    int o[8];
#pragma unroll
    for (int e = 0; e < 8; e++) o[e] = offs[tid][e];
    for (int i = 0; i < NSLOT / 256; i++) {
        int s = s0 + i;
        int e = g_route_e[s];
        int p = o[e]++;
        g_bucket_slot[p] = s;
        g_pos[s] = p;
    }
}

// ---------------- weight fp32 -> bf16 hi/lo split (device-resolved dst) ----------------
__global__ __launch_bounds__(256) void fsplit_kernel(const float* __restrict__ src, int which) {
    __nv_bfloat16 *dh, *dl;
    if (which == 1) { dh = g_w1_h; dl = g_w1_l; }
    else            { dh = g_w2_h; dl = g_w2_l; }
    size_t i = (size_t)blockIdx.x * 256 + threadIdx.x;   // per 4 floats
    float4 v = ((const float4*)src)[i];
    uint32_t h0, l0, h1, l1;
    split2(v.x, v.y, h0, l0);
    split2(v.z, v.w, h1, l1);
    ((uint2*)dh)[i] = make_uint2(h0, h1);
    ((uint2*)dl)[i] = make_uint2(l0, l1);
}

// ---------------- wmma GEMM: 3-stage cp.async ring, 1 barrier/kstep ----------------
template <int KTOT, bool IS_G1>
__global__ __launch_bounds__(256, 2) void gemm_wmma_kernel(const float* __restrict__ bias) {
    constexpr int NC = KTOT / 16;
    constexpr int NDIM = IS_G1 ? PROJ : OUT_DIM;
    extern __shared__ __align__(16) char smx[];
    int* tokS = (int*)(smx + SOFF_TOK);
    float* biasS = (float*)(smx + SOFF_BIAS);

    const int e = g_tile_expert[blockIdx.x];
    if (e < 0) return;
    const int rowbase = g_tile_rowbase[blockIdx.x];
    const int n0 = blockIdx.y * 128;
    const int tid = threadIdx.x, lane = tid & 31, warp = tid >> 5;
    const int wm = warp >> 1, wn = warp & 1;   // warp tile: 32m x 64n
    const uint32_t sbase = smem_u32(smx);

    if (tid < 128) {
        int slot = g_bucket_slot[rowbase + tid];
        tokS[tid] = IS_G1 ? (slot >= 0 ? (slot >> 1) : -1) : slot;
        biasS[tid] = bias[(size_t)e * NDIM + n0 + tid];
    }
    __syncthreads();

    // loader geometry
    const int lr = tid >> 1, lc8 = (tid & 1) * 8;
    const int bk = tid >> 4, bn8 = (tid & 15) * 8;
    const __nv_bfloat16 *pAh, *pAl;
    uint32_t valA = 16;
    if (IS_G1) {
        int tok = tokS[lr];
        if (tok < 0) { valA = 0; tok = 0; }
        pAh = g_x_h + (size_t)tok * IN_DIM + lc8;
        pAl = g_x_l + (size_t)tok * IN_DIM + lc8;
    } else {
        pAh = g_Hh + (size_t)(rowbase + lr) * PROJ + lc8;
        pAl = g_Hl + (size_t)(rowbase + lr) * PROJ + lc8;
    }
    const __nv_bfloat16* Wh = IS_G1 ? g_w1_h : g_w2_h;
    const __nv_bfloat16* Wl = IS_G1 ? g_w1_l : g_w2_l;
    const __nv_bfloat16* pBh = Wh + ((size_t)e * KTOT + bk) * NDIM + n0 + bn8;
    const __nv_bfloat16* pBl = Wl + ((size_t)e * KTOT + bk) * NDIM + n0 + bn8;

    const uint32_t offA = (uint32_t)(lr * APAD + lc8) * 2;
    const uint32_t offB = (uint32_t)(bk * BPAD + bn8) * 2;

#define ISSUE(kidx)                                                         \
    do {                                                                    \
        const uint32_t _s = sbase + (uint32_t)((kidx) % 3) * STG;           \
        const size_t _ka = (size_t)(kidx) * 16;                             \
        CP_ASYNC(_s + offA, pAh + _ka, valA);                               \
        CP_ASYNC(_s + OFF_AL + offA, pAl + _ka, valA);                      \
        CP_ASYNC(_s + OFF_BH + offB, pBh + _ka * NDIM, 16);                 \
        CP_ASYNC(_s + OFF_BL + offB, pBl + _ka * NDIM, 16);                 \
        CP_COMMIT();                                                        \
    } while (0)

    wmma::fragment<wmma::accumulator, 16, 16, 16, float> facc[2][4];
#pragma unroll
    for (int mi = 0; mi < 2; mi++)
#pragma unroll
        for (int ng = 0; ng < 4; ng++) wmma::fill_fragment(facc[mi][ng], 0.f);

    ISSUE(0);
    ISSUE(1);

#pragma unroll 1
    for (int k = 0; k < NC; k++) {
        CP_WAIT1();               // stage k done (only stage k+1 may remain in flight)
        __syncthreads();          // everyone waited; readers of buffer (k+2)%3 are done
        if (k + 2 < NC) { ISSUE(k + 2); } else { CP_COMMIT(); }

        char* bufp = smx + (k % 3) * STG;
        wmma::fragment<wmma::matrix_a, 16, 16, 16, __nv_bfloat16, wmma::row_major> fah[2], fal[2];
#pragma unroll
        for (int mi = 0; mi < 2; mi++) {
            const int ar = wm * 32 + mi * 16;
            wmma::load_matrix_sync(fah[mi], (__nv_bfloat16*)bufp + ar * APAD, APAD);
            wmma::load_matrix_sync(fal[mi], (__nv_bfloat16*)(bufp + OFF_AL) + ar * APAD, APAD);
        }
#pragma unroll
        for (int ng = 0; ng < 4; ng++) {
            wmma::fragment<wmma::matrix_b, 16, 16, 16, __nv_bfloat16, wmma::row_major> fbh, fbl;
            const int bc = wn * 64 + ng * 16;
            wmma::load_matrix_sync(fbh, (__nv_bfloat16*)(bufp + OFF_BH) + bc, BPAD);
            wmma::load_matrix_sync(fbl, (__nv_bfloat16*)(bufp + OFF_BL) + bc, BPAD);
#pragma unroll
            for (int mi = 0; mi < 2; mi++) {
                wmma::mma_sync(facc[mi][ng], fah[mi], fbh, facc[mi][ng]);
                wmma::mma_sync(facc[mi][ng], fal[mi], fbh, facc[mi][ng]);
                wmma::mma_sync(facc[mi][ng], fah[mi], fbl, facc[mi][ng]);
            }
        }
    }

    // ---- epilogue: reuse smem as per-warp patch buffer ----
    __syncthreads();
    float* pw = (float*)smx + warp * 256;
#pragma unroll
    for (int mi = 0; mi < 2; mi++)
#pragma unroll
        for (int ng = 0; ng < 4; ng++) {
            __syncwarp();
            wmma::store_matrix_sync(pw, facc[mi][ng], 16, wmma::mem_row_major);
            __syncwarp();
            const int r = lane >> 1;               // 0..15
            const int c0 = (lane & 1) * 8;         // 0 or 8
            const int mloc = wm * 32 + mi * 16 + r;
            const size_t grow = (size_t)rowbase + mloc;
            const int lcol = wn * 64 + ng * 16 + c0;
            if (IS_G1) {
                float v[8];
#pragma unroll
                for (int j = 0; j < 8; j++)
                    v[j] = gelu_f(pw[r * 16 + c0 + j] + biasS[lcol + j]);
                uint32_t h[4], l[4];
#pragma unroll
                for (int q = 0; q < 4; q++) split2(v[2 * q], v[2 * q + 1], h[q], l[q]);
                *(uint4*)(g_Hh + grow * PROJ + n0 + lcol) = make_uint4(h[0], h[1], h[2], h[3]);
                *(uint4*)(g_Hl + grow * PROJ + n0 + lcol) = make_uint4(l[0], l[1], l[2], l[3]);
            } else {
                const int slot = tokS[mloc];
                if (slot >= 0) {
                    const float w = g_route_w[slot];
                    float* dst = g_Y + grow * OUT_DIM + n0 + lcol;
#pragma unroll
                    for (int j = 0; j < 8; j++)
                        dst[j] = w * (pw[r * 16 + c0 + j] + biasS[lcol + j]);
                }
            }
        }
#undef ISSUE
}

// ---------------- combine (validated) ----------------
__global__ __launch_bounds__(256) void combine_kernel(float* __restrict__ out) {
    int idx = blockIdx.x * 256 + threadIdx.x;
    int t = idx >> 9;
    int c = idx & 511;
    int p0 = g_pos[2 * t], p1 = g_pos[2 * t + 1];
    float4 a = ((const float4*)(g_Y + (size_t)p0 * OUT_DIM))[c];
    float4 b = ((const float4*)(g_Y + (size_t)p1 * OUT_DIM))[c];
    ((float4*)out)[idx] = make_float4(a.x + b.x, a.y + b.y, a.z + b.z, a.w + b.w);
}

extern "C" void kernel_launch(void* const* d_in, const int* in_sizes, int n_in,
                              void* d_out, int out_size) {
    const float* x      = (const float*)d_in[0];
    const float* gate_w = (const float*)d_in[1];
    const float* gate_b = (const float*)d_in[2];
    const float* w1     = (const float*)d_in[3];
    const float* b1     = (const float*)d_in[4];
    const float* w2     = (const float*)d_in[5];
    const float* b2     = (const float*)d_in[6];
    float* out = (float*)d_out;

    cudaFuncSetAttribute(gemm_wmma_kernel<IN_DIM, true>,
                         cudaFuncAttributeMaxDynamicSharedMemorySize, SMEM_DYN);
    cudaFuncSetAttribute(gemm_wmma_kernel<PROJ, false>,
                         cudaFuncAttributeMaxDynamicSharedMemorySize, SMEM_DYN);

    gating_kernel<<<TT / 8, 256>>>(x, gate_w, gate_b);
    fsplit_kernel<<<((size_t)NE * IN_DIM * PROJ / 4) / 256, 256>>>(w1, 1);
    fsplit_kernel<<<((size_t)NE * PROJ * OUT_DIM / 4) / 256, 256>>>(w2, 2);
    bucket_kernel<<<1, 256>>>();
    gemm_wmma_kernel<IN_DIM, true><<<dim3(MAXTILES, PROJ / 128), 256, SMEM_DYN>>>(b1);
    gemm_wmma_kernel<PROJ, false><<<dim3(MAXTILES, OUT_DIM / 128), 256, SMEM_DYN>>>(b2);
    combine_kernel<<<(TT * (OUT_DIM / 4)) / 256, 256>>>(out);
}